// round 5
// baseline (speedup 1.0000x reference)
#include <cuda_runtime.h>
#include <cuda_fp16.h>
#include <cstdint>

// ---------------------------------------------------------------------------
// QLoRA 4-bit: y = x @ (dequant(W)^T + 2 * W_a @ W_b)
//   1) round_xh:   x -> fp16 copy (d_Xh)
//   2) build_weff: NF4 dequant + LoRA fold -> fp16 W_eff[OUT][IN]
//   3) qgemm_h:    fp16 mma.sync m16n8k16, f32 accum. CTA 128x128, BK=32,
//                  256 threads (8 warps, warp tile 32x64), 4-stage cp.async,
//                  ldmatrix.x4. 256 thr => no launch_bounds reg cap => no spill
//                  (round-4 failure mode: 512 thr capped regs at 128 -> spills).
// ---------------------------------------------------------------------------

namespace {
constexpr int D_IN  = 4096;
constexpr int D_OUT = 4096;
constexpr int M_TOK = 8192;
constexpr int RNK   = 16;

constexpr int BM = 128, BN = 128, BK = 32;     // BK halves = 64 bytes
constexpr int KP = 40;                          // padded row (80 B) - conflict-free
constexpr int STAGES = 4;
constexpr int NT = D_IN / BK;                   // 128
constexpr int A_ST_BYTES = BM * KP * 2;         // 10240
constexpr int B_ST_BYTES = BN * KP * 2;         // 10240
constexpr int STAGE_BYTES = A_ST_BYTES + B_ST_BYTES;   // 20480
constexpr int SMEM_DYN = STAGES * STAGE_BYTES;         // 81920
constexpr int NTHREADS = 256;
}

// scratch (allocation-free rule: __device__ globals)
__device__ __align__(16) __half d_Weff[(size_t)D_OUT * D_IN];  // 32 MB
__device__ __align__(16) __half d_Xh[(size_t)M_TOK * D_IN];    // 64 MB

__constant__ float c_nf4[16] = {
    -1.0f, -0.6961928009986877f, -0.5250730514526367f, -0.39491748809814453f,
    -0.28444138169288635f, -0.18477343022823334f, -0.09105003625154495f, 0.0f,
    0.07958029955625534f, 0.16093020141124725f, 0.24611230194568634f,
    0.33791524171829224f, 0.44070982933044434f, 0.5626170039176941f,
    0.7229568362236023f, 1.0f};

__device__ __forceinline__ uint32_t smem_u32(const void* p) {
    uint32_t a;
    asm("{ .reg .u64 t; cvta.to.shared.u64 t, %1; cvt.u32.u64 %0, t; }" : "=r"(a) : "l"(p));
    return a;
}
__device__ __forceinline__ void cp_async16(uint32_t saddr, const void* gaddr) {
    asm volatile("cp.async.cg.shared.global [%0], [%1], 16;\n" :: "r"(saddr), "l"(gaddr));
}
__device__ __forceinline__ void ldsm_x4(uint32_t& r0, uint32_t& r1, uint32_t& r2,
                                        uint32_t& r3, uint32_t addr) {
    asm volatile("ldmatrix.sync.aligned.m8n8.x4.shared.b16 {%0,%1,%2,%3}, [%4];"
                 : "=r"(r0), "=r"(r1), "=r"(r2), "=r"(r3) : "r"(addr));
}
__device__ __forceinline__ void mma16816(float* d, const uint32_t* a, const uint32_t* b) {
    asm volatile(
        "mma.sync.aligned.m16n8k16.row.col.f32.f16.f16.f32 "
        "{%0,%1,%2,%3}, {%4,%5,%6,%7}, {%8,%9}, {%0,%1,%2,%3};\n"
        : "+f"(d[0]), "+f"(d[1]), "+f"(d[2]), "+f"(d[3])
        : "r"(a[0]), "r"(a[1]), "r"(a[2]), "r"(a[3]), "r"(b[0]), "r"(b[1]));
}

// ---------------------------------------------------------------------------
__global__ void round_xh_kernel(const float4* __restrict__ x, uint2* __restrict__ xh, int n4) {
    int i = blockIdx.x * blockDim.x + threadIdx.x;
    int stride = gridDim.x * blockDim.x;
    for (; i < n4; i += stride) {
        float4 v = x[i];
        __half2 lo = __floats2half2_rn(v.x, v.y);
        __half2 hi = __floats2half2_rn(v.z, v.w);
        xh[i] = make_uint2(*reinterpret_cast<uint32_t*>(&lo),
                           *reinterpret_cast<uint32_t*>(&hi));
    }
}

// W_eff[n][k] = nf4[codes[n][k]]*absmax[n][k/64] + 2*sum_r Wa[k][r]*Wb[r][n]
__global__ void build_weff_kernel(const int* __restrict__ codes,
                                  const float* __restrict__ absmax,
                                  const float* __restrict__ Wa,
                                  const float* __restrict__ Wb) {
    const int n = blockIdx.x;
    float wb[RNK];
#pragma unroll
    for (int r = 0; r < RNK; r++) wb[r] = __ldg(&Wb[r * D_OUT + n]);

    const int*   crow = codes  + (size_t)n * D_IN;
    const float* am   = absmax + (size_t)n * (D_IN / 64);
    __half*      orow = d_Weff + (size_t)n * D_IN;

    for (int k = threadIdx.x; k < D_IN; k += blockDim.x) {
        float w = c_nf4[crow[k] & 15] * am[k >> 6];
        const float4* wa = reinterpret_cast<const float4*>(Wa + (size_t)k * RNK);
        float4 a0 = wa[0], a1 = wa[1], a2 = wa[2], a3 = wa[3];
        float l = a0.x * wb[0]  + a0.y * wb[1]  + a0.z * wb[2]  + a0.w * wb[3]
                + a1.x * wb[4]  + a1.y * wb[5]  + a1.z * wb[6]  + a1.w * wb[7]
                + a2.x * wb[8]  + a2.y * wb[9]  + a2.z * wb[10] + a2.w * wb[11]
                + a3.x * wb[12] + a3.y * wb[13] + a3.z * wb[14] + a3.w * wb[15];
        orow[k] = __float2half_rn(w + 2.0f * l);   // SCALE = 2
    }
}

// ---------------------------------------------------------------------------
__global__ __launch_bounds__(NTHREADS)
void qgemm_h(const __half* __restrict__ A, float* __restrict__ C) {
    extern __shared__ char smem[];
    const uint32_t sb = smem_u32(smem);

    const int tid  = threadIdx.x, lane = tid & 31, warp = tid >> 5;
    const int warpM = warp & 3;          // 4 slabs of 32 rows
    const int warpN = warp >> 2;         // 2 slabs of 64 cols
    const int gid = lane >> 2, tig = lane & 3;

    const int mBase = blockIdx.y * BM;
    const int nBase = blockIdx.x * BN;

    const __half* Abase = A      + (size_t)mBase * D_IN;
    const __half* Bbase = d_Weff + (size_t)nBase * D_IN;

    // cp.async chunk map: 128 rows x 4 chunks = 512 per operand, 256 thr x 2
    auto load_stage = [&](int s, int kt) {
        const uint32_t st = sb + s * STAGE_BYTES;
        const char* Ag = (const char*)(Abase) + (size_t)kt * 64;
        const char* Bg = (const char*)(Bbase) + (size_t)kt * 64;
#pragma unroll
        for (int h = 0; h < 2; h++) {
            int idx = tid + h * 256;
            int row = idx >> 2, seg = (idx & 3) << 4;
            cp_async16(st + row * (KP * 2) + seg, Ag + (size_t)row * (D_IN * 2) + seg);
        }
#pragma unroll
        for (int h = 0; h < 2; h++) {
            int idx = tid + h * 256;
            int row = idx >> 2, seg = (idx & 3) << 4;
            cp_async16(st + A_ST_BYTES + row * (KP * 2) + seg,
                       Bg + (size_t)row * (D_IN * 2) + seg);
        }
    };

    float acc[2][8][4];
#pragma unroll
    for (int i = 0; i < 2; i++)
#pragma unroll
        for (int j = 0; j < 8; j++)
#pragma unroll
            for (int v = 0; v < 4; v++) acc[i][j][v] = 0.f;

    // prologue
#pragma unroll
    for (int s = 0; s < STAGES - 1; s++) {
        load_stage(s, s);
        asm volatile("cp.async.commit_group;\n");
    }

    // ldmatrix lane offsets
    const uint32_t aRow = (lane & 15);
    const uint32_t aCol = ((lane >> 4) & 1) << 4;             // bytes
    const uint32_t bRow = (lane & 7) + (((lane >> 4) & 1) << 3);
    const uint32_t bCol = ((lane >> 3) & 1) << 4;             // bytes

    for (int kt = 0; kt < NT; kt++) {
        asm volatile("cp.async.wait_group %0;\n" :: "n"(STAGES - 2));
        __syncthreads();
        const int s = kt & (STAGES - 1);
        const uint32_t Ast = sb + s * STAGE_BYTES;
        const uint32_t Bst = Ast + A_ST_BYTES;

#pragma unroll
        for (int kh = 0; kh < 2; kh++) {           // two k16 halves of BK=32
            uint32_t a[2][4];
#pragma unroll
            for (int mi = 0; mi < 2; mi++) {
                uint32_t addr = Ast + (warpM * 32 + mi * 16 + aRow) * (KP * 2)
                              + kh * 32 + aCol;
                ldsm_x4(a[mi][0], a[mi][1], a[mi][2], a[mi][3], addr);
            }
            uint32_t b[8][2];
#pragma unroll
            for (int nb = 0; nb < 4; nb++) {
                uint32_t r0, r1, r2, r3;
                uint32_t addr = Bst + (warpN * 64 + nb * 16 + bRow) * (KP * 2)
                              + kh * 32 + bCol;
                ldsm_x4(r0, r1, r2, r3, addr);
                b[2 * nb][0] = r0; b[2 * nb][1] = r1;
                b[2 * nb + 1][0] = r2; b[2 * nb + 1][1] = r3;
            }
#pragma unroll
            for (int mi = 0; mi < 2; mi++)
#pragma unroll
                for (int ni = 0; ni < 8; ni++)
                    mma16816(acc[mi][ni], a[mi], b[ni]);
        }

        if (kt + STAGES - 1 < NT)
            load_stage((kt + STAGES - 1) & (STAGES - 1), kt + STAGES - 1);
        asm volatile("cp.async.commit_group;\n");
    }

    // epilogue: float2 stores
#pragma unroll
    for (int mi = 0; mi < 2; mi++) {
        const int row0 = mBase + warpM * 32 + mi * 16 + gid;
#pragma unroll
        for (int ni = 0; ni < 8; ni++) {
            const int col = nBase + warpN * 64 + ni * 8 + tig * 2;
            *reinterpret_cast<float2*>(C + (size_t)row0 * D_OUT + col) =
                make_float2(acc[mi][ni][0], acc[mi][ni][1]);
            *reinterpret_cast<float2*>(C + (size_t)(row0 + 8) * D_OUT + col) =
                make_float2(acc[mi][ni][2], acc[mi][ni][3]);
        }
    }
}

// ---------------------------------------------------------------------------
extern "C" void kernel_launch(void* const* d_in, const int* in_sizes, int n_in,
                              void* d_out, int out_size) {
    const float* x      = (const float*)d_in[0];
    const int*   codes  = (const int*)  d_in[1];
    const float* absmax = (const float*)d_in[2];
    const float* Wa     = (const float*)d_in[3];
    const float* Wb     = (const float*)d_in[4];
    float* out = (float*)d_out;

    cudaFuncSetAttribute(qgemm_h, cudaFuncAttributeMaxDynamicSharedMemorySize, SMEM_DYN);

    round_xh_kernel<<<4096, 256>>>((const float4*)x, (uint2*)d_Xh,
                                   (int)((size_t)M_TOK * D_IN / 4));
    build_weff_kernel<<<D_OUT, 256>>>(codes, absmax, Wa, Wb);

    dim3 grid(D_OUT / BN, M_TOK / BM);   // (32, 64), n-fast for W_eff L2 reuse
    qgemm_h<<<grid, NTHREADS, SMEM_DYN>>>(d_Xh, out);
}

// round 7
// speedup vs baseline: 1.7349x; 1.7349x over previous
#include <cuda_runtime.h>
#include <cuda_fp16.h>
#include <cstdint>

// ---------------------------------------------------------------------------
// QLoRA 4-bit: y = x @ (dequant(W)^T + 2 * W_a @ W_b)
//   1) round_xh:   x -> fp16 (d_Xh), MLP=4 batched loads
//   2) build_weff: NF4 dequant + LoRA fold -> fp16 W_eff, smem LUT
//   3) qgemm_h:    round-2 proven skeleton (2-stage cp.async, scalar-LDS
//                  fragments, 128x128 CTA, 8 warps, warp tile 32x64) with
//                  dtype fp16 + mma.m16n8k16 as the ONLY change. NO ldmatrix.
// ---------------------------------------------------------------------------

namespace {
constexpr int D_IN  = 4096;
constexpr int D_OUT = 4096;
constexpr int M_TOK = 8192;
constexpr int RNK   = 16;

constexpr int BM = 128, BN = 128, BK = 32;   // BK halves = 64 B/row
constexpr int KP = 40;                        // row pitch in halves (80 B)
constexpr int NT = D_IN / BK;                 // 128 k-tiles
constexpr int NTHREADS = 256;
}

// scratch (allocation-free rule: __device__ globals)
__device__ __align__(16) __half d_Weff[(size_t)D_OUT * D_IN];  // 32 MB
__device__ __align__(16) __half d_Xh[(size_t)M_TOK * D_IN];    // 64 MB

__device__ const float g_nf4[16] = {
    -1.0f, -0.6961928009986877f, -0.5250730514526367f, -0.39491748809814453f,
    -0.28444138169288635f, -0.18477343022823334f, -0.09105003625154495f, 0.0f,
    0.07958029955625534f, 0.16093020141124725f, 0.24611230194568634f,
    0.33791524171829224f, 0.44070982933044434f, 0.5626170039176941f,
    0.7229568362236023f, 1.0f};

__device__ __forceinline__ uint32_t h2u(__half2 h) {
    return *reinterpret_cast<uint32_t*>(&h);
}
__device__ __forceinline__ uint32_t smem_u32(const void* p) {
    uint32_t a;
    asm("{ .reg .u64 t; cvta.to.shared.u64 t, %1; cvt.u32.u64 %0, t; }" : "=r"(a) : "l"(p));
    return a;
}
__device__ __forceinline__ void cp_async16(uint32_t saddr, const void* gaddr) {
    asm volatile("cp.async.ca.shared.global [%0], [%1], 16;\n" :: "r"(saddr), "l"(gaddr));
}
__device__ __forceinline__ void mma16816(float* d, const uint32_t* a, const uint32_t* b) {
    asm volatile(
        "mma.sync.aligned.m16n8k16.row.col.f32.f16.f16.f32 "
        "{%0,%1,%2,%3}, {%4,%5,%6,%7}, {%8,%9}, {%0,%1,%2,%3};\n"
        : "+f"(d[0]), "+f"(d[1]), "+f"(d[2]), "+f"(d[3])
        : "r"(a[0]), "r"(a[1]), "r"(a[2]), "r"(a[3]), "r"(b[0]), "r"(b[1]));
}

// ---------------------------------------------------------------------------
// x (fp32) -> fp16, 4 independent LDG.128 in flight per iteration (MLP=4).
__global__ void round_xh_kernel(const float4* __restrict__ x, uint2* __restrict__ xh,
                                int n4) {                  // n4 = elems/4
    int i = blockIdx.x * blockDim.x + threadIdx.x;
    const int stride = gridDim.x * blockDim.x;
    for (; i < n4; i += 4 * stride) {
        int i1 = i + stride, i2 = i + 2 * stride, i3 = i + 3 * stride;
        float4 v0 = x[i];
        float4 v1 = (i1 < n4) ? x[i1] : v0;
        float4 v2 = (i2 < n4) ? x[i2] : v0;
        float4 v3 = (i3 < n4) ? x[i3] : v0;
        xh[i] = make_uint2(h2u(__floats2half2_rn(v0.x, v0.y)),
                           h2u(__floats2half2_rn(v0.z, v0.w)));
        if (i1 < n4) xh[i1] = make_uint2(h2u(__floats2half2_rn(v1.x, v1.y)),
                                         h2u(__floats2half2_rn(v1.z, v1.w)));
        if (i2 < n4) xh[i2] = make_uint2(h2u(__floats2half2_rn(v2.x, v2.y)),
                                         h2u(__floats2half2_rn(v2.z, v2.w)));
        if (i3 < n4) xh[i3] = make_uint2(h2u(__floats2half2_rn(v3.x, v3.y)),
                                         h2u(__floats2half2_rn(v3.z, v3.w)));
    }
}

// W_eff[n][k] = nf4[codes[n][k]]*absmax[n][k/64] + 2*sum_r Wa[k][r]*Wb[r][n]
__global__ void build_weff_kernel(const int4* __restrict__ codes4,
                                  const float* __restrict__ absmax,
                                  const float* __restrict__ Wa,
                                  const float* __restrict__ Wb) {
    __shared__ float lut[16];
    const int n = blockIdx.x;
    if (threadIdx.x < 16) lut[threadIdx.x] = g_nf4[threadIdx.x];
    float wb[RNK];
#pragma unroll
    for (int r = 0; r < RNK; r++) wb[r] = __ldg(&Wb[r * D_OUT + n]);
    __syncthreads();

    const int4*  crow = codes4 + (size_t)n * (D_IN / 4);
    const float* am   = absmax + (size_t)n * (D_IN / 64);
    uint2*       orow = reinterpret_cast<uint2*>(d_Weff + (size_t)n * D_IN);

    for (int g = threadIdx.x; g < D_IN / 4; g += blockDim.x) {
        const int4 c = crow[g];
        const float s = am[g >> 4];
        const int k0 = g * 4;
        float v[4] = {lut[c.x & 15] * s, lut[c.y & 15] * s,
                      lut[c.z & 15] * s, lut[c.w & 15] * s};
#pragma unroll
        for (int j = 0; j < 4; j++) {
            const float4* wa = reinterpret_cast<const float4*>(Wa + (size_t)(k0 + j) * RNK);
            float4 a0 = wa[0], a1 = wa[1], a2 = wa[2], a3 = wa[3];
            float l = a0.x * wb[0]  + a0.y * wb[1]  + a0.z * wb[2]  + a0.w * wb[3]
                    + a1.x * wb[4]  + a1.y * wb[5]  + a1.z * wb[6]  + a1.w * wb[7]
                    + a2.x * wb[8]  + a2.y * wb[9]  + a2.z * wb[10] + a2.w * wb[11]
                    + a3.x * wb[12] + a3.y * wb[13] + a3.z * wb[14] + a3.w * wb[15];
            v[j] += 2.0f * l;                   // SCALE = 2
        }
        orow[g] = make_uint2(h2u(__floats2half2_rn(v[0], v[1])),
                             h2u(__floats2half2_rn(v[2], v[3])));
    }
}

// ---------------------------------------------------------------------------
__global__ __launch_bounds__(NTHREADS)
void qgemm_h(const __half* __restrict__ A, float* __restrict__ C) {
    __shared__ __align__(16) __half As[2][BM][KP];
    __shared__ __align__(16) __half Bs[2][BN][KP];

    const int tid  = threadIdx.x, lane = tid & 31, warp = tid >> 5;
    const int warpM = warp & 3;          // 4 slabs of 32 rows
    const int warpN = warp >> 2;         // 2 slabs of 64 cols
    const int gid = lane >> 2, tig = lane & 3;

    const int mBase = blockIdx.y * BM;
    const int nBase = blockIdx.x * BN;

    const int ldRow = tid >> 2;          // 0..63
    const int ldSeg = (tid & 3) << 4;    // byte offset 0,16,32,48

    const char* Agp = (const char*)(A      + (size_t)(mBase + ldRow) * D_IN) + ldSeg;
    const char* Bgp = (const char*)(d_Weff + (size_t)(nBase + ldRow) * D_IN) + ldSeg;
    const uint32_t sAs = smem_u32(&As[0][0][0]);
    const uint32_t sBs = smem_u32(&Bs[0][0][0]);
    constexpr int STG = BM * KP * 2;     // one stage of one operand, bytes

    float acc[2][8][4];
#pragma unroll
    for (int i = 0; i < 2; i++)
#pragma unroll
        for (int j = 0; j < 8; j++)
#pragma unroll
            for (int v = 0; v < 4; v++) acc[i][j][v] = 0.f;

    // prologue: stages 0,1  (each thread: 2 A-chunks + 2 B-chunks of 16B)
#pragma unroll
    for (int s = 0; s < 2; s++) {
        const int k0b = s * BK * 2;      // byte offset along K
#pragma unroll
        for (int h = 0; h < 2; h++) {
            const uint32_t so = (ldRow + 64 * h) * (KP * 2) + ldSeg;
            cp_async16(sAs + s * STG + so, Agp + (size_t)(64 * h) * (D_IN * 2) + k0b);
            cp_async16(sBs + s * STG + so, Bgp + (size_t)(64 * h) * (D_IN * 2) + k0b);
        }
        asm volatile("cp.async.commit_group;\n");
    }

    for (int kt = 0; kt < NT; kt++) {
        asm volatile("cp.async.wait_group 1;\n");
        __syncthreads();
        const int buf = kt & 1;

#pragma unroll
        for (int kh = 0; kh < 2; kh++) {            // two k16 halves of BK=32
            const int kb = kh * 16;
            uint32_t a[2][4];
#pragma unroll
            for (int mi = 0; mi < 2; mi++) {
                const int r = warpM * 32 + mi * 16 + gid;
                a[mi][0] = *(const uint32_t*)&As[buf][r    ][kb + 2 * tig];
                a[mi][1] = *(const uint32_t*)&As[buf][r + 8][kb + 2 * tig];
                a[mi][2] = *(const uint32_t*)&As[buf][r    ][kb + 2 * tig + 8];
                a[mi][3] = *(const uint32_t*)&As[buf][r + 8][kb + 2 * tig + 8];
            }
            uint32_t b[8][2];
#pragma unroll
            for (int ni = 0; ni < 8; ni++) {
                const int c = warpN * 64 + ni * 8 + gid;
                b[ni][0] = *(const uint32_t*)&Bs[buf][c][kb + 2 * tig];
                b[ni][1] = *(const uint32_t*)&Bs[buf][c][kb + 2 * tig + 8];
            }
#pragma unroll
            for (int mi = 0; mi < 2; mi++)
#pragma unroll
                for (int ni = 0; ni < 8; ni++)
                    mma16816(acc[mi][ni], a[mi], b[ni]);
        }
        __syncthreads();

        if (kt + 2 < NT) {
            const int k0b = (kt + 2) * BK * 2;
#pragma unroll
            for (int h = 0; h < 2; h++) {
                const uint32_t so = (ldRow + 64 * h) * (KP * 2) + ldSeg;
                cp_async16(sAs + buf * STG + so, Agp + (size_t)(64 * h) * (D_IN * 2) + k0b);
                cp_async16(sBs + buf * STG + so, Bgp + (size_t)(64 * h) * (D_IN * 2) + k0b);
            }
        }
        asm volatile("cp.async.commit_group;\n");
    }

    // epilogue: float2 stores
#pragma unroll
    for (int mi = 0; mi < 2; mi++) {
        const int row0 = mBase + warpM * 32 + mi * 16 + gid;
#pragma unroll
        for (int ni = 0; ni < 8; ni++) {
            const int col = nBase + warpN * 64 + ni * 8 + tig * 2;
            *reinterpret_cast<float2*>(C + (size_t)row0 * D_OUT + col) =
                make_float2(acc[mi][ni][0], acc[mi][ni][1]);
            *reinterpret_cast<float2*>(C + (size_t)(row0 + 8) * D_OUT + col) =
                make_float2(acc[mi][ni][2], acc[mi][ni][3]);
        }
    }
}

// ---------------------------------------------------------------------------
extern "C" void kernel_launch(void* const* d_in, const int* in_sizes, int n_in,
                              void* d_out, int out_size) {
    const float* x      = (const float*)d_in[0];
    const int*   codes  = (const int*)  d_in[1];
    const float* absmax = (const float*)d_in[2];
    const float* Wa     = (const float*)d_in[3];
    const float* Wb     = (const float*)d_in[4];
    float* out = (float*)d_out;

    round_xh_kernel<<<2048, 256>>>((const float4*)x, (uint2*)d_Xh,
                                   (int)((size_t)M_TOK * D_IN / 4));
    build_weff_kernel<<<D_OUT, 256>>>((const int4*)codes, absmax, Wa, Wb);

    dim3 grid(D_OUT / BN, M_TOK / BM);   // (32, 64), n-fast for W_eff L2 reuse
    qgemm_h<<<grid, NTHREADS>>>(d_Xh, out);
}

// round 8
// speedup vs baseline: 9.0294x; 5.2046x over previous
#include <cuda_runtime.h>
#include <cstdint>

// ---------------------------------------------------------------------------
// QLoRA 4-bit: y = x @ (dequant(W)^T + 2 * W_a @ W_b)
//   1) build_weff: NF4 dequant + LoRA fold -> fp32 W_eff (tf32-pre-rounded)
//   2) qgemm:      TF32 m16n8k8 GEMM (the proven-fast legacy mma on sm_103a),
//                  round-2 skeleton, but fragments fed by ldmatrix-for-tf32
//                  (8x8 b16 tile == 8x4 fp32 tile): 6 ldmatrix.x4 replace 24
//                  scalar LDS per warp-k8. x read as raw fp32; cvt.rna on A
//                  fragments in-loop (round_x prologue eliminated, -372us).
// fp16/m16n8k16 abandoned: measured ~10x slower per instruction on sm_103a.
// ---------------------------------------------------------------------------

namespace {
constexpr int D_IN  = 4096;
constexpr int D_OUT = 4096;
constexpr int M_TOK = 8192;
constexpr int RNK   = 16;

constexpr int BM = 128, BN = 128, BK = 16;   // BK floats = 64 B/row
constexpr int KP = 20;                        // row pitch floats (80 B, 16B-mult)
constexpr int NT = D_IN / BK;                 // 256 k-tiles
constexpr int NTHREADS = 256;
}

// scratch (allocation-free rule: __device__ global)
__device__ __align__(16) float d_Weff[(size_t)D_OUT * D_IN];   // 64 MB

__device__ const float g_nf4[16] = {
    -1.0f, -0.6961928009986877f, -0.5250730514526367f, -0.39491748809814453f,
    -0.28444138169288635f, -0.18477343022823334f, -0.09105003625154495f, 0.0f,
    0.07958029955625534f, 0.16093020141124725f, 0.24611230194568634f,
    0.33791524171829224f, 0.44070982933044434f, 0.5626170039176941f,
    0.7229568362236023f, 1.0f};

__device__ __forceinline__ unsigned f2tf32(float x) {
    unsigned r;
    asm("cvt.rna.tf32.f32 %0, %1;" : "=r"(r) : "f"(x));
    return r;
}
__device__ __forceinline__ uint32_t smem_u32(const void* p) {
    uint32_t a;
    asm("{ .reg .u64 t; cvta.to.shared.u64 t, %1; cvt.u32.u64 %0, t; }" : "=r"(a) : "l"(p));
    return a;
}
__device__ __forceinline__ void cp_async16(uint32_t saddr, const void* gaddr) {
    asm volatile("cp.async.ca.shared.global [%0], [%1], 16;\n" :: "r"(saddr), "l"(gaddr));
}
__device__ __forceinline__ void ldsm_x4(uint32_t& r0, uint32_t& r1, uint32_t& r2,
                                        uint32_t& r3, uint32_t addr) {
    asm volatile("ldmatrix.sync.aligned.m8n8.x4.shared.b16 {%0,%1,%2,%3}, [%4];"
                 : "=r"(r0), "=r"(r1), "=r"(r2), "=r"(r3) : "r"(addr));
}
__device__ __forceinline__ void mma_tf32(float* d, const unsigned* a, const unsigned* b) {
    asm volatile(
        "mma.sync.aligned.m16n8k8.row.col.f32.tf32.tf32.f32 "
        "{%0,%1,%2,%3}, {%4,%5,%6,%7}, {%8,%9}, {%0,%1,%2,%3};\n"
        : "+f"(d[0]), "+f"(d[1]), "+f"(d[2]), "+f"(d[3])
        : "r"(a[0]), "r"(a[1]), "r"(a[2]), "r"(a[3]), "r"(b[0]), "r"(b[1]));
}

// ---------------------------------------------------------------------------
// W_eff[n][k] = nf4[codes[n][k]]*absmax[n][k/64] + 2*sum_r Wa[k][r]*Wb[r][n]
// tf32-pre-rounded fp32 output (B side needs no in-loop cvt).
__global__ void build_weff_kernel(const int4* __restrict__ codes4,
                                  const float* __restrict__ absmax,
                                  const float* __restrict__ Wa,
                                  const float* __restrict__ Wb) {
    __shared__ float lut[16];
    const int n = blockIdx.x;
    if (threadIdx.x < 16) lut[threadIdx.x] = g_nf4[threadIdx.x];
    float wb[RNK];
#pragma unroll
    for (int r = 0; r < RNK; r++) wb[r] = __ldg(&Wb[r * D_OUT + n]);
    __syncthreads();

    const int4*  crow = codes4 + (size_t)n * (D_IN / 4);
    const float* am   = absmax + (size_t)n * (D_IN / 64);
    float4*      orow = reinterpret_cast<float4*>(d_Weff + (size_t)n * D_IN);

    for (int g = threadIdx.x; g < D_IN / 4; g += blockDim.x) {
        const int4 c = crow[g];
        const float s = am[g >> 4];
        const int k0 = g * 4;
        float v[4] = {lut[c.x & 15] * s, lut[c.y & 15] * s,
                      lut[c.z & 15] * s, lut[c.w & 15] * s};
#pragma unroll
        for (int j = 0; j < 4; j++) {
            const float4* wa = reinterpret_cast<const float4*>(Wa + (size_t)(k0 + j) * RNK);
            float4 a0 = wa[0], a1 = wa[1], a2 = wa[2], a3 = wa[3];
            float l = a0.x * wb[0]  + a0.y * wb[1]  + a0.z * wb[2]  + a0.w * wb[3]
                    + a1.x * wb[4]  + a1.y * wb[5]  + a1.z * wb[6]  + a1.w * wb[7]
                    + a2.x * wb[8]  + a2.y * wb[9]  + a2.z * wb[10] + a2.w * wb[11]
                    + a3.x * wb[12] + a3.y * wb[13] + a3.z * wb[14] + a3.w * wb[15];
            v[j] += 2.0f * l;                   // SCALE = 2
        }
        orow[g] = make_float4(__uint_as_float(f2tf32(v[0])),
                              __uint_as_float(f2tf32(v[1])),
                              __uint_as_float(f2tf32(v[2])),
                              __uint_as_float(f2tf32(v[3])));
    }
}

// ---------------------------------------------------------------------------
// TF32 GEMM: C[M][N] = x[M][K] * W_eff[N][K]^T.  Round-2 skeleton:
// 128x128x16 tile, 8 warps (4M x 2N, warp tile 32x64), 2-stage cp.async.
// Fragments via ldmatrix (b16 8x8 == fp32 8x4 quadrants).
__global__ __launch_bounds__(NTHREADS)
void qgemm(const float* __restrict__ A, float* __restrict__ C) {
    __shared__ __align__(16) float As[2][BM][KP];
    __shared__ __align__(16) float Bs[2][BN][KP];

    const int tid  = threadIdx.x, lane = tid & 31, warp = tid >> 5;
    const int warpM = warp & 3;          // 32-row slab
    const int warpN = warp >> 2;         // 64-col slab
    const int gid = lane >> 2, tig = lane & 3;

    const int mBase = blockIdx.y * BM;
    const int nBase = blockIdx.x * BN;

    const int ldRow = tid >> 2;          // 0..63
    const int ldCol = (tid & 3) << 2;    // float offset 0,4,8,12

    const float* Agp = A      + (size_t)(mBase + ldRow) * D_IN + ldCol;
    const float* Bgp = d_Weff + (size_t)(nBase + ldRow) * D_IN + ldCol;
    const uint32_t sAs = smem_u32(&As[0][0][0]);
    const uint32_t sBs = smem_u32(&Bs[0][0][0]);
    constexpr int STG = BM * KP * 4;     // one operand stage, bytes (10240)

    // ldmatrix per-lane address components (m = lane>>3 selects quadrant,
    // j = lane&7 the row within it)
    const int lm_m = lane >> 3, lm_j = lane & 7;
    // A quadrants: m0:(r+0..7,k0-3) m1:(r+8..15,k0-3) m2:(r+0..7,k4-7) m3:(r+8..15,k4-7)
    const uint32_t aRowOff = ((lm_m & 1) * 8 + lm_j) * (KP * 4);
    const uint32_t aColOff = (lm_m >> 1) * 16;       // bytes
    // B quadrants: m0:(n+0..7,k0-3) m1:(n+0..7,k4-7) m2:(n+8..15,k0-3) m3:(n+8..15,k4-7)
    const uint32_t bRowOff = ((lm_m >> 1) * 8 + lm_j) * (KP * 4);
    const uint32_t bColOff = (lm_m & 1) * 16;        // bytes

    float acc[2][8][4];
#pragma unroll
    for (int i = 0; i < 2; i++)
#pragma unroll
        for (int j = 0; j < 8; j++)
#pragma unroll
            for (int v = 0; v < 4; v++) acc[i][j][v] = 0.f;

    // prologue: stages 0,1
#pragma unroll
    for (int s = 0; s < 2; s++) {
        const int k0 = s * BK;
#pragma unroll
        for (int h = 0; h < 2; h++) {
            const uint32_t so = (ldRow + 64 * h) * (KP * 4) + ldCol * 4;
            cp_async16(sAs + s * STG + so, Agp + (size_t)(64 * h) * D_IN + k0);
            cp_async16(sBs + s * STG + so, Bgp + (size_t)(64 * h) * D_IN + k0);
        }
        asm volatile("cp.async.commit_group;\n");
    }

    for (int kt = 0; kt < NT; kt++) {
        asm volatile("cp.async.wait_group 1;\n");
        __syncthreads();
        const int buf = kt & 1;
        const uint32_t Ab = sAs + buf * STG;
        const uint32_t Bb = sBs + buf * STG;

#pragma unroll
        for (int kk = 0; kk < BK; kk += 8) {
            unsigned a[2][4];
#pragma unroll
            for (int mi = 0; mi < 2; mi++) {
                uint32_t r0, r1, r2, r3;
                const uint32_t addr = Ab + (warpM * 32 + mi * 16) * (KP * 4)
                                    + aRowOff + kk * 4 + aColOff;
                ldsm_x4(r0, r1, r2, r3, addr);
                a[mi][0] = f2tf32(__uint_as_float(r0));
                a[mi][1] = f2tf32(__uint_as_float(r1));
                a[mi][2] = f2tf32(__uint_as_float(r2));
                a[mi][3] = f2tf32(__uint_as_float(r3));
            }
            unsigned b[8][2];
#pragma unroll
            for (int np = 0; np < 4; np++) {         // 2 ni per ldmatrix.x4
                uint32_t r0, r1, r2, r3;
                const uint32_t addr = Bb + (warpN * 64 + np * 16) * (KP * 4)
                                    + bRowOff + kk * 4 + bColOff;
                ldsm_x4(r0, r1, r2, r3, addr);       // W_eff pre-rounded
                b[2 * np][0] = r0;  b[2 * np][1] = r1;
                b[2 * np + 1][0] = r2;  b[2 * np + 1][1] = r3;
            }
#pragma unroll
            for (int mi = 0; mi < 2; mi++)
#pragma unroll
                for (int ni = 0; ni < 8; ni++)
                    mma_tf32(acc[mi][ni], a[mi], b[ni]);
        }
        __syncthreads();

        if (kt + 2 < NT) {
            const int k0 = (kt + 2) * BK;
#pragma unroll
            for (int h = 0; h < 2; h++) {
                const uint32_t so = (ldRow + 64 * h) * (KP * 4) + ldCol * 4;
                cp_async16(sAs + buf * STG + so, Agp + (size_t)(64 * h) * D_IN + k0);
                cp_async16(sBs + buf * STG + so, Bgp + (size_t)(64 * h) * D_IN + k0);
            }
        }
        asm volatile("cp.async.commit_group;\n");
    }

    // epilogue: float2 stores
#pragma unroll
    for (int mi = 0; mi < 2; mi++) {
        const int row0 = mBase + warpM * 32 + mi * 16 + gid;
#pragma unroll
        for (int ni = 0; ni < 8; ni++) {
            const int col = nBase + warpN * 64 + ni * 8 + tig * 2;
            *reinterpret_cast<float2*>(C + (size_t)row0 * D_OUT + col) =
                make_float2(acc[mi][ni][0], acc[mi][ni][1]);
            *reinterpret_cast<float2*>(C + (size_t)(row0 + 8) * D_OUT + col) =
                make_float2(acc[mi][ni][2], acc[mi][ni][3]);
        }
    }
}

// ---------------------------------------------------------------------------
extern "C" void kernel_launch(void* const* d_in, const int* in_sizes, int n_in,
                              void* d_out, int out_size) {
    const float* x      = (const float*)d_in[0];
    const int*   codes  = (const int*)  d_in[1];
    const float* absmax = (const float*)d_in[2];
    const float* Wa     = (const float*)d_in[3];
    const float* Wb     = (const float*)d_in[4];
    float* out = (float*)d_out;

    build_weff_kernel<<<D_OUT, 256>>>((const int4*)codes, absmax, Wa, Wb);

    dim3 grid(D_OUT / BN, M_TOK / BM);   // (32, 64), n-fast for W_eff L2 reuse
    qgemm<<<grid, NTHREADS>>>(x, out);
}